// round 1
// baseline (speedup 1.0000x reference)
#include <cuda_runtime.h>
#include <math.h>

#define Bb 128
#define Nn 1024
#define Dd 768
#define Cc 28
#define TDd 1536
#define Kk 16
#define HH 8
#define HDd 96

// ---------------- scratch (device globals; no allocation allowed) -------------
__device__ float g_g[Bb*Kk*Dd];     // sel / running graph state  [2048,768]
__device__ float g_msg[Bb*Kk*Dd];   // adj @ g                    [2048,768]
__device__ float g_tmp[Bb*Kk*Dd];   // GEMM output                [2048,768]
__device__ float g_km[Bb*Kk*Dd];    // K projection               [2048,768]
__device__ float g_vm[Bb*Kk*Dd];    // V projection               [2048,768]
__device__ float g_adj[Bb*Kk*Kk];
__device__ int   g_tidx[Bb*Kk];
__device__ float g_tsc[Bb*Kk];
__device__ float g_lq[Cc*Dd];
__device__ float g_q[Cc*Dd];
__device__ float g_m[Cc*Dd];
__device__ float g_bconst[Cc];

// ---------------- 1) scorer: relu(x@sw1+sb1)@sw2+sb2 -> sigmoid ---------------
// M=131072, N=192, K=768 GEMM fused with the 192->1 reduction.
// Block: 64 rows x 192 cols, 256 threads (16x16), thread tile 4x12.
__global__ void scorer_kernel(const float* __restrict__ x,
                              const float* __restrict__ sw1,
                              const float* __restrict__ sb1,
                              const float* __restrict__ sw2,
                              const float* __restrict__ sb2,
                              float* __restrict__ scores)
{
    __shared__ float As[16][68];     // [k][m], padded
    __shared__ float Bs[16][196];    // [k][n], padded
    const int tid = threadIdx.x;
    const int tx = tid & 15, ty = tid >> 4;
    const int m0 = blockIdx.x * 64;

    float acc[4][12];
#pragma unroll
    for (int i = 0; i < 4; i++)
#pragma unroll
        for (int j = 0; j < 12; j++) acc[i][j] = 0.f;

    const int lrow = tid >> 2;          // 0..63
    const int lkc  = (tid & 3) * 4;     // 0,4,8,12
    const int bk   = tid >> 4;          // 0..15
    const int bn   = (tid & 15) * 12;   // 0..180

    for (int kt = 0; kt < 768; kt += 16) {
        float4 a = *reinterpret_cast<const float4*>(
            &x[(size_t)(m0 + lrow) * 768 + kt + lkc]);
        As[lkc + 0][lrow] = a.x; As[lkc + 1][lrow] = a.y;
        As[lkc + 2][lrow] = a.z; As[lkc + 3][lrow] = a.w;

        const float* bsrc = &sw1[(size_t)(kt + bk) * 192 + bn];
        float4 b0 = *reinterpret_cast<const float4*>(bsrc + 0);
        float4 b1 = *reinterpret_cast<const float4*>(bsrc + 4);
        float4 b2 = *reinterpret_cast<const float4*>(bsrc + 8);
        *reinterpret_cast<float4*>(&Bs[bk][bn + 0]) = b0;
        *reinterpret_cast<float4*>(&Bs[bk][bn + 4]) = b1;
        *reinterpret_cast<float4*>(&Bs[bk][bn + 8]) = b2;
        __syncthreads();

#pragma unroll
        for (int kk = 0; kk < 16; kk++) {
            float4 a4 = *reinterpret_cast<float4*>(&As[kk][ty * 4]);
            float ar[4] = {a4.x, a4.y, a4.z, a4.w};
            float4 c0 = *reinterpret_cast<float4*>(&Bs[kk][tx * 12 + 0]);
            float4 c1 = *reinterpret_cast<float4*>(&Bs[kk][tx * 12 + 4]);
            float4 c2 = *reinterpret_cast<float4*>(&Bs[kk][tx * 12 + 8]);
            float br[12] = {c0.x,c0.y,c0.z,c0.w,c1.x,c1.y,c1.z,c1.w,c2.x,c2.y,c2.z,c2.w};
#pragma unroll
            for (int i = 0; i < 4; i++)
#pragma unroll
                for (int j = 0; j < 12; j++) acc[i][j] += ar[i] * br[j];
        }
        __syncthreads();
    }

    // epilogue: relu(h + sb1) . sw2 per row, reduce over 16 col-threads
    float part[4] = {0.f, 0.f, 0.f, 0.f};
#pragma unroll
    for (int j = 0; j < 12; j++) {
        int c = tx * 12 + j;
        float b1v = sb1[c];
        float w2v = sw2[c];
#pragma unroll
        for (int i = 0; i < 4; i++)
            part[i] += fmaxf(acc[i][j] + b1v, 0.f) * w2v;
    }
#pragma unroll
    for (int off = 8; off > 0; off >>= 1)
#pragma unroll
        for (int i = 0; i < 4; i++)
            part[i] += __shfl_down_sync(0xffffffffu, part[i], off, 16);

    if (tx == 0) {
        float b2v = sb2[0];
#pragma unroll
        for (int i = 0; i < 4; i++) {
            float z = part[i] + b2v;
            scores[m0 + ty * 4 + i] = 1.f / (1.f + expf(-z));
        }
    }
}

// ---------------- 2) top-k (K=16) per batch, ties -> lower index ---------------
__global__ void topk_kernel(const float* __restrict__ scores, float* __restrict__ out_idx)
{
    __shared__ float vals[1024];
    __shared__ float sv[256];
    __shared__ int   si[256];
    const int b = blockIdx.x, t = threadIdx.x;
    for (int i = t; i < 1024; i += 256) vals[i] = scores[b * 1024 + i];
    __syncthreads();
    for (int it = 0; it < 16; it++) {
        float bv = -1e30f; int bi = 0;
        for (int i = t; i < 1024; i += 256) {
            float v = vals[i];
            if (v > bv) { bv = v; bi = i; }
        }
        sv[t] = bv; si[t] = bi;
        __syncthreads();
        for (int s = 128; s > 0; s >>= 1) {
            if (t < s) {
                float v2 = sv[t + s]; int i2 = si[t + s];
                if (v2 > sv[t] || (v2 == sv[t] && i2 < si[t])) { sv[t] = v2; si[t] = i2; }
            }
            __syncthreads();
        }
        if (t == 0) {
            int w = si[0];
            g_tidx[b * 16 + it] = w;
            g_tsc[b * 16 + it]  = sv[0];
            out_idx[b * 16 + it] = (float)w;
            vals[w] = -1e30f;
        }
        __syncthreads();
    }
}

// -------- 3) gather selected patches, scale, cosine-sim adjacency softmax -----
__global__ void seladj_kernel(const float* __restrict__ x, float* __restrict__ out_adj)
{
    const int b = blockIdx.x, t = threadIdx.x;
    __shared__ int   idxS[16];
    __shared__ float scS[16];
    __shared__ float nrmS[16];
    if (t < 16) { idxS[t] = g_tidx[b * 16 + t]; scS[t] = g_tsc[b * 16 + t]; }
    __syncthreads();
    for (int e = t; e < 16 * 768; e += 256) {
        int k = e / 768, d = e - k * 768;
        g_g[(size_t)(b * 16 + k) * 768 + d] =
            x[((size_t)b * 1024 + idxS[k]) * 768 + d] * scS[k];
    }
    __syncthreads();
    // row norms: 8 warps, 2 rows each
    int w = t >> 5, lane = t & 31;
    for (int r = w; r < 16; r += 8) {
        const float* row = &g_g[(size_t)(b * 16 + r) * 768];
        float s = 0.f;
        for (int d = lane; d < 768; d += 32) { float v = row[d]; s += v * v; }
#pragma unroll
        for (int o = 16; o > 0; o >>= 1) s += __shfl_down_sync(0xffffffffu, s, o);
        if (lane == 0) nrmS[r] = fmaxf(sqrtf(s), 1e-12f);
    }
    __syncthreads();
    // sim[i][j] with thread (i,j); 256 threads = 16x16
    const int i = t >> 4, j = t & 15;
    const float* ri = &g_g[(size_t)(b * 16 + i) * 768];
    const float* rj = &g_g[(size_t)(b * 16 + j) * 768];
    float dot = 0.f;
    for (int d = 0; d < 768; d += 4) {
        float4 va = *reinterpret_cast<const float4*>(&ri[d]);
        float4 vb = *reinterpret_cast<const float4*>(&rj[d]);
        dot += va.x * vb.x + va.y * vb.y + va.z * vb.z + va.w * vb.w;
    }
    float sim = 10.f * dot / (nrmS[i] * nrmS[j]);
    float mx = sim;
#pragma unroll
    for (int o = 8; o > 0; o >>= 1) mx = fmaxf(mx, __shfl_xor_sync(0xffffffffu, mx, o, 16));
    float ev = expf(sim - mx);
    float sum = ev;
#pragma unroll
    for (int o = 8; o > 0; o >>= 1) sum += __shfl_xor_sync(0xffffffffu, sum, o, 16);
    float a = ev / sum;
    g_adj[b * 256 + i * 16 + j] = a;
    out_adj[b * 256 + i * 16 + j] = a;
}

// ---------------- 4a) msg = adj @ g (per batch) -------------------------------
__global__ void msg_kernel()
{
    const int b = blockIdx.x, t = threadIdx.x;
    __shared__ float adjS[256];
    adjS[t] = g_adj[b * 256 + t];
    __syncthreads();
    for (int d = t; d < 768; d += 256) {
        float col[16];
#pragma unroll
        for (int j = 0; j < 16; j++) col[j] = g_g[(size_t)(b * 16 + j) * 768 + d];
#pragma unroll
        for (int k = 0; k < 16; k++) {
            float s = 0.f;
#pragma unroll
            for (int j = 0; j < 16; j++) s += adjS[k * 16 + j] * col[j];
            g_msg[(size_t)(b * 16 + k) * 768 + d] = s;
        }
    }
}

// ---------------- 4b) generic fp32 GEMM C = A@B + bias  (M%64==0,N%64==0,K%16==0)
__global__ void gemm64_kernel(const float* __restrict__ A, const float* __restrict__ Bm,
                              const float* __restrict__ bias, float* __restrict__ Cm,
                              int M, int N, int Kd)
{
    __shared__ float As[16][68];
    __shared__ float Bs[16][64];
    const int tid = threadIdx.x;
    const int tx = tid & 15, ty = tid >> 4;
    const int m0 = blockIdx.y * 64, n0 = blockIdx.x * 64;
    float acc[4][4];
#pragma unroll
    for (int i = 0; i < 4; i++)
#pragma unroll
        for (int j = 0; j < 4; j++) acc[i][j] = 0.f;

    const int lrow = tid >> 2, lkc = (tid & 3) * 4;
    const int bk = tid >> 4, bn = (tid & 15) * 4;

    for (int kt = 0; kt < Kd; kt += 16) {
        float4 a = *reinterpret_cast<const float4*>(&A[(size_t)(m0 + lrow) * Kd + kt + lkc]);
        As[lkc + 0][lrow] = a.x; As[lkc + 1][lrow] = a.y;
        As[lkc + 2][lrow] = a.z; As[lkc + 3][lrow] = a.w;
        *reinterpret_cast<float4*>(&Bs[bk][bn]) =
            *reinterpret_cast<const float4*>(&Bm[(size_t)(kt + bk) * N + n0 + bn]);
        __syncthreads();
#pragma unroll
        for (int kk = 0; kk < 16; kk++) {
            float4 a4 = *reinterpret_cast<float4*>(&As[kk][ty * 4]);
            float4 b4 = *reinterpret_cast<float4*>(&Bs[kk][tx * 4]);
            float ar[4] = {a4.x, a4.y, a4.z, a4.w};
            float br[4] = {b4.x, b4.y, b4.z, b4.w};
#pragma unroll
            for (int i = 0; i < 4; i++)
#pragma unroll
                for (int j = 0; j < 4; j++) acc[i][j] += ar[i] * br[j];
        }
        __syncthreads();
    }
#pragma unroll
    for (int i = 0; i < 4; i++) {
        float4 o;
        o.x = acc[i][0] + bias[n0 + tx * 4 + 0];
        o.y = acc[i][1] + bias[n0 + tx * 4 + 1];
        o.z = acc[i][2] + bias[n0 + tx * 4 + 2];
        o.w = acc[i][3] + bias[n0 + tx * 4 + 3];
        *reinterpret_cast<float4*>(&Cm[(size_t)(m0 + ty * 4 + i) * N + n0 + tx * 4]) = o;
    }
}

// ---------------- 4c) g += relu(LayerNorm(tmp)) -------------------------------
__global__ void lnrelu_kernel(const float* __restrict__ tmp,
                              const float* __restrict__ gam,
                              const float* __restrict__ bet)
{
    const int row = blockIdx.x, t = threadIdx.x;
    __shared__ float sS[8], ssS[8];
    __shared__ float stat[2];
    float v[3], s = 0.f, ss = 0.f;
#pragma unroll
    for (int q = 0; q < 3; q++) {
        v[q] = tmp[(size_t)row * 768 + t + q * 256];
        s += v[q]; ss += v[q] * v[q];
    }
#pragma unroll
    for (int o = 16; o > 0; o >>= 1) {
        s  += __shfl_down_sync(0xffffffffu, s, o);
        ss += __shfl_down_sync(0xffffffffu, ss, o);
    }
    int w = t >> 5, lane = t & 31;
    if (lane == 0) { sS[w] = s; ssS[w] = ss; }
    __syncthreads();
    if (t == 0) {
        float S = 0.f, SS = 0.f;
#pragma unroll
        for (int i = 0; i < 8; i++) { S += sS[i]; SS += ssS[i]; }
        float mu = S / 768.f;
        float var = SS / 768.f - mu * mu;
        stat[0] = mu; stat[1] = rsqrtf(var + 1e-5f);
    }
    __syncthreads();
    float mu = stat[0], inv = stat[1];
#pragma unroll
    for (int q = 0; q < 3; q++) {
        int d = t + q * 256;
        float o = (v[q] - mu) * inv * gam[d] + bet[d];
        g_g[(size_t)row * 768 + d] += fmaxf(o, 0.f);
    }
}

// ---------------- 5) label-query precompute (batch independent) ----------------
__global__ void lq_kernel(const float* __restrict__ le, const float* __restrict__ lp_w,
                          const float* __restrict__ lp_b)
{
    const int c = blockIdx.y, d0 = blockIdx.x * 128, t = threadIdx.x;
    __shared__ float leS[1536];
    __shared__ float part[128];
    for (int i = t; i < 1536; i += 256) leS[i] = le[c * 1536 + i];
    __syncthreads();
    const int dl = t & 127, half = t >> 7;
    const int d = d0 + dl, k0 = half * 768;
    float s = 0.f;
#pragma unroll 4
    for (int k = 0; k < 768; k++) s += leS[k0 + k] * lp_w[(size_t)(k0 + k) * 768 + d];
    if (half) part[dl] = s;
    __syncthreads();
    if (!half) g_lq[c * 768 + d] = s + part[dl] + lp_b[d];
}

__global__ void qm_kernel(const float* __restrict__ wq, const float* __restrict__ bq,
                          const float* __restrict__ wo)
{
    const int c = blockIdx.y, e0 = blockIdx.x * 128, t = threadIdx.x;
    __shared__ float lqS[768];
    __shared__ float pq[128], pm[128];
    for (int i = t; i < 768; i += 256) lqS[i] = g_lq[c * 768 + i];
    __syncthreads();
    const int el = t & 127, half = t >> 7;
    const int e = e0 + el, k0 = half * 384;
    float sq = 0.f, sm = 0.f;
    const float* worow = &wo[(size_t)e * 768];
#pragma unroll 4
    for (int d = k0; d < k0 + 384; d++) {
        sq += lqS[d] * wq[(size_t)d * 768 + e];
        sm += worow[d] * lqS[d];
    }
    if (half) { pq[el] = sq; pm[el] = sm; }
    __syncthreads();
    if (!half) {
        g_q[c * 768 + e] = sq + pq[el] + bq[e];
        g_m[c * 768 + e] = sm + pm[el];
    }
}

__global__ void bconst_kernel(const float* __restrict__ bo)
{
    const int c = blockIdx.x, lane = threadIdx.x;
    float s = 0.f;
    for (int d = lane; d < 768; d += 32) s += bo[d] * g_lq[c * 768 + d];
#pragma unroll
    for (int o = 16; o > 0; o >>= 1) s += __shfl_down_sync(0xffffffffu, s, o);
    if (lane == 0) g_bconst[c] = s;
}

// ---------------- 6) fused attention + logits (per batch) ----------------------
__global__ void attn_kernel(const float* __restrict__ scale_p,
                            float* __restrict__ out_logits,
                            float* __restrict__ out_aw)
{
    const int b = blockIdx.x, t = threadIdx.x;
    __shared__ float sS[8 * 28 * 16];   // att scores [h][c][k]
    __shared__ float wS[8 * 16 * 28];   // v.m        [h][k][c]
    const float invs = rsqrtf(96.f);

    for (int task = t; task < 3584; task += 256) {
        const int k = task & 15;
        const int c = (task >> 4) % 28;
        const int h = task / (16 * 28);
        const float* qp = &g_q[c * 768 + h * 96];
        const float* kp = &g_km[(size_t)(b * 16 + k) * 768 + h * 96];
        const float* mp = &g_m[c * 768 + h * 96];
        const float* vp = &g_vm[(size_t)(b * 16 + k) * 768 + h * 96];
        float dq = 0.f, dv = 0.f;
#pragma unroll
        for (int d = 0; d < 96; d += 4) {
            float4 qa = *reinterpret_cast<const float4*>(&qp[d]);
            float4 kb = *reinterpret_cast<const float4*>(&kp[d]);
            float4 ma = *reinterpret_cast<const float4*>(&mp[d]);
            float4 vb = *reinterpret_cast<const float4*>(&vp[d]);
            dq += qa.x * kb.x + qa.y * kb.y + qa.z * kb.z + qa.w * kb.w;
            dv += ma.x * vb.x + ma.y * vb.y + ma.z * vb.z + ma.w * vb.w;
        }
        sS[task] = dq * invs;
        wS[(h * 16 + k) * 28 + c] = dv;
    }
    __syncthreads();
    // softmax over k (rows = h*28+c)
    if (t < 224) {
        float* row = &sS[t * 16];
        float mx = row[0];
#pragma unroll
        for (int k = 1; k < 16; k++) mx = fmaxf(mx, row[k]);
        float sum = 0.f;
#pragma unroll
        for (int k = 0; k < 16; k++) { float e = expf(row[k] - mx); row[k] = e; sum += e; }
        float r = 1.f / sum;
#pragma unroll
        for (int k = 0; k < 16; k++) row[k] *= r;
    }
    __syncthreads();
    // attn_weights = mean over heads
    for (int e = t; e < 448; e += 256) {
        const int c = e >> 4, k = e & 15;
        float s = 0.f;
#pragma unroll
        for (int h = 0; h < 8; h++) s += sS[(h * 28 + c) * 16 + k];
        out_aw[(b * 28 + c) * 16 + k] = s * 0.125f;
    }
    // logits
    if (t < 224) {
        const int c = t >> 3, h = t & 7;
        float s = 0.f;
#pragma unroll
        for (int k = 0; k < 16; k++) s += sS[(h * 28 + c) * 16 + k] * wS[(h * 16 + k) * 28 + c];
#pragma unroll
        for (int o = 4; o > 0; o >>= 1) s += __shfl_down_sync(0xffffffffu, s, o, 8);
        if (h == 0) out_logits[b * 28 + c] = scale_p[0] * (s + g_bconst[c]);
    }
}

// ------------------------------- launch ---------------------------------------
extern "C" void kernel_launch(void* const* d_in, const int* in_sizes, int n_in,
                              void* d_out, int out_size)
{
    const float* x     = (const float*)d_in[0];
    const float* le    = (const float*)d_in[1];
    const float* sw1   = (const float*)d_in[2];
    const float* sb1   = (const float*)d_in[3];
    const float* sw2   = (const float*)d_in[4];
    const float* sb2   = (const float*)d_in[5];
    const float* gcn_w = (const float*)d_in[6];
    const float* gcn_b = (const float*)d_in[7];
    const float* ln_g  = (const float*)d_in[8];
    const float* ln_b  = (const float*)d_in[9];
    const float* lp_w  = (const float*)d_in[10];
    const float* lp_b  = (const float*)d_in[11];
    const float* wq    = (const float*)d_in[12];
    const float* wk    = (const float*)d_in[13];
    const float* wv    = (const float*)d_in[14];
    const float* bq    = (const float*)d_in[15];
    const float* bk_   = (const float*)d_in[16];
    const float* bv    = (const float*)d_in[17];
    const float* wo    = (const float*)d_in[18];
    const float* bo    = (const float*)d_in[19];
    const float* scale = (const float*)d_in[20];

    float* out = (float*)d_out;
    float* out_logits = out;                         // [128,28]
    float* out_scores = out + 3584;                  // [128,1024,1]
    float* out_idx    = out_scores + 131072;         // [128,16] (as float)
    float* out_adj    = out_idx + 2048;              // [128,16,16]
    float* out_aw     = out_adj + 32768;             // [128,28,16]

    float *p_msg, *p_tmp, *p_g, *p_k, *p_v;
    cudaGetSymbolAddress((void**)&p_msg, g_msg);
    cudaGetSymbolAddress((void**)&p_tmp, g_tmp);
    cudaGetSymbolAddress((void**)&p_g,   g_g);
    cudaGetSymbolAddress((void**)&p_k,   g_km);
    cudaGetSymbolAddress((void**)&p_v,   g_vm);

    // batch-independent label precompute
    lq_kernel<<<dim3(6, 28), 256>>>(le, lp_w, lp_b);
    qm_kernel<<<dim3(6, 28), 256>>>(wq, bq, wo);
    bconst_kernel<<<28, 32>>>(bo);

    // scorer + topk + gather/adjacency
    scorer_kernel<<<2048, 256>>>(x, sw1, sb1, sw2, sb2, out_scores);
    topk_kernel<<<128, 256>>>(out_scores, out_idx);
    seladj_kernel<<<128, 256>>>(x, out_adj);

    // GCN layers
    for (int i = 0; i < 2; i++) {
        msg_kernel<<<128, 256>>>();
        gemm64_kernel<<<dim3(12, 32), 256>>>(p_msg, gcn_w + (size_t)i * 768 * 768,
                                             gcn_b + i * 768, p_tmp, 2048, 768, 768);
        lnrelu_kernel<<<2048, 256>>>(p_tmp, ln_g + i * 768, ln_b + i * 768);
    }

    // K, V projections
    gemm64_kernel<<<dim3(12, 32), 256>>>(p_g, wk, bk_, p_k, 2048, 768, 768);
    gemm64_kernel<<<dim3(12, 32), 256>>>(p_g, wv, bv, p_v, 2048, 768, 768);

    // attention + logits + attn_weights
    attn_kernel<<<128, 256>>>(scale, out_logits, out_aw);
}